// round 6
// baseline (speedup 1.0000x reference)
#include <cuda_runtime.h>
#include <cstdint>

static constexpr int N_OUT = 40962;
static constexpr int NIDX  = N_OUT * 7;          // 286734
static constexpr int OUTC  = 128;
static constexpr int BM    = 64;
static constexpr int GEMM_GRID = (N_OUT + BM - 1) / BM;   // 641

// ---------------- device scratch (no allocations allowed) ----------------
__device__ int   g_neigh[NIDX];
__device__ int   g_pool[NIDX];
__device__ float g_pooled[(size_t)N_OUT * 64];
__device__ float g_t1[(size_t)N_OUT * OUTC];
__device__ float g_h [(size_t)N_OUT * OUTC];
__device__ float g_t2[(size_t)N_OUT * OUTC];
__device__ float g_w1[448 * 128];
__device__ float g_w2[896 * 128];
__device__ float g_part[GEMM_GRID * 256];        // per-GEMM-block partial sum/sumsq
__device__ float g_bnp[256];                     // scale (0..127), shift (128..255)

// ---------------- helpers ----------------
__device__ __forceinline__ float f2tf32(float x) {
    uint32_t r;
    asm("cvt.rna.tf32.f32 %0, %1;" : "=r"(r) : "f"(x));
    return __uint_as_float(r);
}
__device__ __forceinline__ void mma_tf32(float* d, const uint32_t* a, const uint32_t* b) {
    asm volatile(
        "mma.sync.aligned.m16n8k8.row.col.f32.tf32.tf32.f32 "
        "{%0,%1,%2,%3}, {%4,%5,%6,%7}, {%8,%9}, {%0,%1,%2,%3};\n"
        : "+f"(d[0]), "+f"(d[1]), "+f"(d[2]), "+f"(d[3])
        : "r"(a[0]), "r"(a[1]), "r"(a[2]), "r"(a[3]), "r"(b[0]), "r"(b[1]));
}
__device__ __forceinline__ void cp16(float* smem_dst, const float* gsrc) {
    uint32_t s = (uint32_t)__cvta_generic_to_shared(smem_dst);
    asm volatile("cp.async.cg.shared.global [%0], [%1], 16;\n" :: "r"(s), "l"(gsrc));
}
__device__ __forceinline__ void cp_commit() { asm volatile("cp.async.commit_group;\n"); }
template <int N>
__device__ __forceinline__ void cp_wait() { asm volatile("cp.async.wait_group %0;\n" :: "n"(N)); }

// ---------------- index dtype detect + convert (both arrays, one launch) ----------------
__global__ void convert_idx2_kernel(const int* __restrict__ rawA, int* __restrict__ outA,
                                    const int* __restrict__ rawB, int* __restrict__ outB, int n) {
    const int half = gridDim.x / 2;
    const int* raw = (blockIdx.x < half) ? rawA : rawB;
    int*       out = (blockIdx.x < half) ? outA : outB;
    const int  b   = (blockIdx.x < half) ? blockIdx.x : blockIdx.x - half;
    __shared__ int s_is64;
    if (threadIdx.x == 0) s_is64 = 1;
    __syncthreads();
    for (int i = threadIdx.x; i < 1024; i += blockDim.x)
        if (raw[2 * i + 1] != 0) s_is64 = 0;
    __syncthreads();
    const int f = s_is64;
    for (int i = b * blockDim.x + threadIdx.x; i < n; i += half * blockDim.x)
        out[i] = f ? raw[2 * i] : raw[i];
}

// ---------------- weights -> tf32 ----------------
__global__ void wconv_kernel(const float* __restrict__ W1, const float* __restrict__ W2) {
    int i = blockIdx.x * blockDim.x + threadIdx.x;
    if (i < 448 * 128) g_w1[i] = f2tf32(W1[i]);
    else { int j = i - 448 * 128; if (j < 896 * 128) g_w2[j] = f2tf32(W2[j]); }
}

// ---------------- 1-ring mean pool (reference reshape scramble), tf32 output ----------------
// 16 nodes per block, 16 threads per node, float4 gathers (MLP=7 per thread).
__global__ void __launch_bounds__(256) pool_kernel(const float* __restrict__ x) {
    __shared__ float sh[16][448];
    __shared__ int   srow[16][7];
    const int tid  = threadIdx.x;
    const int slot = tid >> 4;
    const int q    = tid & 15;
    const int node0 = blockIdx.x * 16;

    if (tid < 112) {
        int s = tid / 7, j = tid % 7;
        int node = node0 + s;
        srow[s][j] = (node < N_OUT) ? g_pool[node * 7 + j] : 0;
    }
    __syncthreads();
#pragma unroll
    for (int j = 0; j < 7; j++) {
        const float4 v = *((const float4*)(x + (size_t)srow[slot][j] * 64) + q);
        *(float4*)&sh[slot][j * 64 + q * 4] = v;
    }
    __syncthreads();

    const int node = node0 + slot;
    if (node < N_OUT) {
#pragma unroll
        for (int p = 0; p < 4; p++) {
            int c = q + 16 * p;
            float s = 0.f;
#pragma unroll
            for (int k = 0; k < 7; k++) s += sh[slot][c * 7 + k];
            g_pooled[(size_t)node * 64 + c] = f2tf32(s * (1.0f / 7.0f));
        }
    }
}

// ---------------- gather-fused TF32 GEMM, cp.async 2-stage, fused BN partials ----------------
// BM=64, BN=128, BK=32.  8 warps in 2(M) x 4(N), warp tile 32x32.
// out[M,128] = gather(in)[M,7C] @ W[7C,128] + bias; per-block sum/sumsq -> part.
template <int C>
__global__ void __launch_bounds__(256, 3) gather_gemm_tf32(
    const float* __restrict__ in, const int* __restrict__ neigh,
    const float* __restrict__ W, const float* __restrict__ bias,
    float* __restrict__ out, float* __restrict__ part)
{
    constexpr int K   = 7 * C;
    constexpr int NT  = K / 32;
    constexpr int ASZ = BM * 36;
    constexpr int BSZ = 32 * 136;
    constexpr int STG = ASZ + BSZ;

    extern __shared__ float smem[];          // 2 * STG floats
    __shared__ int   rows[BM * 7];
    __shared__ float red_s[2][128];
    __shared__ float red_q[2][128];

    const int tid  = threadIdx.x;
    const int m0   = blockIdx.x * BM;
    const int lane = tid & 31;
    const int wid  = tid >> 5;
    const int wm   = (wid & 1) * 32;        // m offset (0 or 32)
    const int wn   = (wid >> 1) * 32;       // n offset (0,32,64,96)
    const int g    = lane >> 2;
    const int tig  = lane & 3;

    for (int i = tid; i < BM * 7; i += 256) {
        int node = m0 + (i / 7);
        rows[i] = (node < N_OUT) ? neigh[node * 7 + (i % 7)] : 0;
    }
    __syncthreads();

    auto issue = [&](int t) {
        const int k0 = t * 32;
        const int j  = k0 / C;
        const int c0 = k0 % C;
        float* dstA = smem + (t & 1) * STG;
        float* dstB = dstA + ASZ;
#pragma unroll
        for (int p = 0; p < 2; p++) {       // 64 rows x 32 k = 512 float4
            int q  = tid + p * 256;
            int m  = q >> 3;
            int kv = (q & 7) << 2;
            cp16(&dstA[m * 36 + kv], &in[(size_t)rows[m * 7 + j] * C + c0 + kv]);
        }
#pragma unroll
        for (int p = 0; p < 4; p++) {       // 32 k x 128 cols = 1024 float4
            int q   = tid + p * 256;
            int kl  = q >> 5;
            int col = (q & 31) << 2;
            cp16(&dstB[kl * 136 + col], &W[(size_t)(k0 + kl) * 128 + col]);
        }
        cp_commit();
    };

    issue(0);
    issue(1);

    float acc[2][4][4];
#pragma unroll
    for (int mt = 0; mt < 2; mt++)
#pragma unroll
        for (int nt = 0; nt < 4; nt++)
#pragma unroll
            for (int i = 0; i < 4; i++) acc[mt][nt][i] = 0.f;

    for (int t = 0; t < NT; t++) {
        if (t < NT - 1) cp_wait<1>(); else cp_wait<0>();
        __syncthreads();

        const float* Ab = smem + (t & 1) * STG;
        const float* Bb = Ab + ASZ;
#pragma unroll
        for (int kk = 0; kk < 4; kk++) {
            const int kb = kk * 8;
            uint32_t a[2][4];
#pragma unroll
            for (int mt = 0; mt < 2; mt++) {
                int r = wm + mt * 16 + g;
                a[mt][0] = __float_as_uint(Ab[r * 36 + kb + tig]);
                a[mt][1] = __float_as_uint(Ab[(r + 8) * 36 + kb + tig]);
                a[mt][2] = __float_as_uint(Ab[r * 36 + kb + tig + 4]);
                a[mt][3] = __float_as_uint(Ab[(r + 8) * 36 + kb + tig + 4]);
            }
            uint32_t b[4][2];
#pragma unroll
            for (int nt = 0; nt < 4; nt++) {
                b[nt][0] = __float_as_uint(Bb[(kb + tig) * 136 + wn + nt * 8 + g]);
                b[nt][1] = __float_as_uint(Bb[(kb + tig + 4) * 136 + wn + nt * 8 + g]);
            }
#pragma unroll
            for (int mt = 0; mt < 2; mt++)
#pragma unroll
                for (int nt = 0; nt < 4; nt++)
                    mma_tf32(acc[mt][nt], a[mt], b[nt]);
        }
        __syncthreads();
        if (t + 2 < NT) issue(t + 2);
    }

    // ---- epilogue: bias, store, per-column sum/sumsq (valid rows only) ----
    float cs[8], cq[8];
#pragma unroll
    for (int i = 0; i < 8; i++) { cs[i] = 0.f; cq[i] = 0.f; }

#pragma unroll
    for (int mt = 0; mt < 2; mt++) {
        int r0 = m0 + wm + mt * 16 + g;
        bool v0 = r0 < N_OUT, v1 = (r0 + 8) < N_OUT;
#pragma unroll
        for (int nt = 0; nt < 4; nt++) {
            int col = wn + nt * 8 + 2 * tig;
            float2 bv = *(const float2*)&bias[col];
            float o00 = acc[mt][nt][0] + bv.x, o01 = acc[mt][nt][1] + bv.y;
            float o10 = acc[mt][nt][2] + bv.x, o11 = acc[mt][nt][3] + bv.y;
            if (v0) {
                *(float2*)&out[(size_t)r0 * OUTC + col] = make_float2(o00, o01);
                cs[nt*2]   += o00; cq[nt*2]   += o00 * o00;
                cs[nt*2+1] += o01; cq[nt*2+1] += o01 * o01;
            }
            if (v1) {
                *(float2*)&out[(size_t)(r0 + 8) * OUTC + col] = make_float2(o10, o11);
                cs[nt*2]   += o10; cq[nt*2]   += o10 * o10;
                cs[nt*2+1] += o11; cq[nt*2+1] += o11 * o11;
            }
        }
    }
#pragma unroll
    for (int i = 0; i < 8; i++) {
#pragma unroll
        for (int d = 4; d < 32; d <<= 1) {
            cs[i] += __shfl_xor_sync(0xffffffffu, cs[i], d);
            cq[i] += __shfl_xor_sync(0xffffffffu, cq[i], d);
        }
    }
    if (lane < 4) {   // g == 0, tig = lane; warps with same wn differ in (wid&1)
#pragma unroll
        for (int nt = 0; nt < 4; nt++) {
            int col = wn + nt * 8 + 2 * lane;
            red_s[wid & 1][col]     = cs[nt*2];
            red_s[wid & 1][col + 1] = cs[nt*2+1];
            red_q[wid & 1][col]     = cq[nt*2];
            red_q[wid & 1][col + 1] = cq[nt*2+1];
        }
    }
    __syncthreads();
    if (tid < 128) {
        part[blockIdx.x * 256 + tid]       = red_s[0][tid] + red_s[1][tid];
        part[blockIdx.x * 256 + 128 + tid] = red_q[0][tid] + red_q[1][tid];
    }
}

// ---------------- BN finalize + apply ----------------
__global__ void finalize_kernel(const float* __restrict__ gamma,
                                const float* __restrict__ beta, int n_rows) {
    const int ch = threadIdx.x;  // 128 threads
    float s = 0.f, ss = 0.f;
#pragma unroll 4
    for (int b = 0; b < GEMM_GRID; b++) {
        s  += g_part[b * 256 + ch];
        ss += g_part[b * 256 + 128 + ch];
    }
    float m  = s / n_rows;
    float v  = ss / n_rows - m * m;          // biased variance
    float r  = rsqrtf(v + 1e-5f);
    float sc = r * gamma[ch];
    g_bnp[ch]       = sc;
    g_bnp[128 + ch] = beta[ch] - m * sc;
}

template <bool CVT>
__global__ void bn_kernel(const float* __restrict__ t, float* __restrict__ out, int n_rows) {
    __shared__ float sc[128], sb[128];
    if (threadIdx.x < 128) {
        sc[threadIdx.x] = g_bnp[threadIdx.x];
        sb[threadIdx.x] = g_bnp[128 + threadIdx.x];
    }
    __syncthreads();
    const int total = n_rows * OUTC;
    for (int i = blockIdx.x * blockDim.x + threadIdx.x; i < total;
         i += gridDim.x * blockDim.x) {
        float y = t[i] * sc[i & 127] + sb[i & 127];
        y = (y >= 0.f) ? y : 0.2f * y;
        out[i] = CVT ? f2tf32(y) : y;
    }
}

// ---------------- launch ----------------
extern "C" void kernel_launch(void* const* d_in, const int* in_sizes, int n_in,
                              void* d_out, int out_size) {
    const float* x    = (const float*)d_in[0];
    const int*   nraw = (const int*)d_in[1];
    const int*   praw = (const int*)d_in[2];
    const float* W1   = (const float*)d_in[3];
    const float* b1   = (const float*)d_in[4];
    const float* g1   = (const float*)d_in[5];
    const float* be1  = (const float*)d_in[6];
    const float* W2   = (const float*)d_in[7];
    const float* b2   = (const float*)d_in[8];
    const float* g2   = (const float*)d_in[9];
    const float* be2  = (const float*)d_in[10];
    float* out = (float*)d_out;

    int *p_neigh, *p_pool;
    float *p_pooled, *p_t1, *p_h, *p_t2, *p_w1, *p_w2, *p_part;
    cudaGetSymbolAddress((void**)&p_neigh,  g_neigh);
    cudaGetSymbolAddress((void**)&p_pool,   g_pool);
    cudaGetSymbolAddress((void**)&p_pooled, g_pooled);
    cudaGetSymbolAddress((void**)&p_t1,     g_t1);
    cudaGetSymbolAddress((void**)&p_h,      g_h);
    cudaGetSymbolAddress((void**)&p_t2,     g_t2);
    cudaGetSymbolAddress((void**)&p_w1,     g_w1);
    cudaGetSymbolAddress((void**)&p_w2,     g_w2);
    cudaGetSymbolAddress((void**)&p_part,   g_part);

    const int SMEM_DYN = 2 * (BM * 36 + 32 * 136) * (int)sizeof(float);  // 53248
    cudaFuncSetAttribute(gather_gemm_tf32<64>,
                         cudaFuncAttributeMaxDynamicSharedMemorySize, SMEM_DYN);
    cudaFuncSetAttribute(gather_gemm_tf32<128>,
                         cudaFuncAttributeMaxDynamicSharedMemorySize, SMEM_DYN);

    convert_idx2_kernel<<<224, 256>>>(nraw, p_neigh, praw, p_pool, NIDX);
    wconv_kernel<<<(448 * 128 + 896 * 128 + 255) / 256, 256>>>(W1, W2);

    pool_kernel<<<(N_OUT + 15) / 16, 256>>>(x);

    gather_gemm_tf32<64><<<GEMM_GRID, 256, SMEM_DYN>>>(p_pooled, p_neigh, p_w1, b1, p_t1, p_part);
    finalize_kernel<<<1, 128>>>(g1, be1, N_OUT);
    bn_kernel<true><<<512, 256>>>(p_t1, p_h, N_OUT);

    gather_gemm_tf32<128><<<GEMM_GRID, 256, SMEM_DYN>>>(p_h, p_neigh, p_w2, b2, p_t2, p_part);
    finalize_kernel<<<1, 128>>>(g2, be2, N_OUT);
    bn_kernel<false><<<512, 256>>>(p_t2, out, N_OUT);
}

// round 7
// speedup vs baseline: 1.1428x; 1.1428x over previous
#include <cuda_runtime.h>
#include <cstdint>

static constexpr int N_OUT = 40962;
static constexpr int NIDX  = N_OUT * 7;          // 286734
static constexpr int OUTC  = 128;
static constexpr int GEMM_GRID = (N_OUT + 127) / 128;   // 321

// ---------------- device scratch (no allocations allowed) ----------------
__device__ int   g_neigh[NIDX];
__device__ int   g_pool[NIDX];
__device__ float g_pooled[(size_t)N_OUT * 64];   // channel-pair-permuted
__device__ float g_t1[(size_t)N_OUT * OUTC];     // normal order
__device__ float g_h [(size_t)N_OUT * OUTC];     // channel-pair-permuted
__device__ float g_t2[(size_t)N_OUT * OUTC];     // normal order
__device__ float g_w1[14 * 128 * 32];            // [ktile][col][k'] permuted tf32
__device__ float g_w2[28 * 128 * 32];            // [ktile][col][k'] permuted tf32
__device__ float g_part[GEMM_GRID * 256];        // per-GEMM-block partial sum/sumsq
__device__ float g_bnp[256];                     // scale (0..127), shift (128..255)

// Channel permutation within each 8-group: orig k = a + 4b  <->  k' = 2a + b
__device__ __forceinline__ int perm8(int c) {
    return (c & ~7) | (((c & 3) << 1) | ((c >> 2) & 1));
}

// ---------------- helpers ----------------
__device__ __forceinline__ float f2tf32(float x) {
    uint32_t r;
    asm("cvt.rna.tf32.f32 %0, %1;" : "=r"(r) : "f"(x));
    return __uint_as_float(r);
}
__device__ __forceinline__ void mma_tf32(float* d, const uint32_t* a, const uint32_t* b) {
    asm volatile(
        "mma.sync.aligned.m16n8k8.row.col.f32.tf32.tf32.f32 "
        "{%0,%1,%2,%3}, {%4,%5,%6,%7}, {%8,%9}, {%0,%1,%2,%3};\n"
        : "+f"(d[0]), "+f"(d[1]), "+f"(d[2]), "+f"(d[3])
        : "r"(a[0]), "r"(a[1]), "r"(a[2]), "r"(a[3]), "r"(b[0]), "r"(b[1]));
}
__device__ __forceinline__ void cp16(float* smem_dst, const float* gsrc) {
    uint32_t s = (uint32_t)__cvta_generic_to_shared(smem_dst);
    asm volatile("cp.async.cg.shared.global [%0], [%1], 16;\n" :: "r"(s), "l"(gsrc));
}
__device__ __forceinline__ void cp_commit() { asm volatile("cp.async.commit_group;\n"); }
template <int N>
__device__ __forceinline__ void cp_wait() { asm volatile("cp.async.wait_group %0;\n" :: "n"(N)); }

// ---------------- index dtype detect + convert (both arrays, one launch) ----------------
__global__ void convert_idx2_kernel(const int* __restrict__ rawA, int* __restrict__ outA,
                                    const int* __restrict__ rawB, int* __restrict__ outB, int n) {
    const int half = gridDim.x / 2;
    const int* raw = (blockIdx.x < half) ? rawA : rawB;
    int*       out = (blockIdx.x < half) ? outA : outB;
    const int  b   = (blockIdx.x < half) ? blockIdx.x : blockIdx.x - half;
    __shared__ int s_is64;
    if (threadIdx.x == 0) s_is64 = 1;
    __syncthreads();
    for (int i = threadIdx.x; i < 1024; i += blockDim.x)
        if (raw[2 * i + 1] != 0) s_is64 = 0;
    __syncthreads();
    const int f = s_is64;
    for (int i = b * blockDim.x + threadIdx.x; i < n; i += half * blockDim.x)
        out[i] = f ? raw[2 * i] : raw[i];
}

// ---------------- weights -> tf32, tile-major [ktile][col][k'] with pair permutation ------
__global__ void wconv_kernel(const float* __restrict__ W1, const float* __restrict__ W2) {
    int i = blockIdx.x * blockDim.x + threadIdx.x;
    if (i < 14 * 4096) {
        int t = i >> 12, rem = i & 4095;
        int col = rem >> 5, cp = rem & 31;
        int w = cp & 7;
        int k = t * 32 + (cp & ~7) + (w >> 1) + 4 * (w & 1);
        g_w1[i] = f2tf32(W1[k * 128 + col]);
    } else {
        int j = i - 14 * 4096;
        if (j < 28 * 4096) {
            int t = j >> 12, rem = j & 4095;
            int col = rem >> 5, cp = rem & 31;
            int w = cp & 7;
            int k = t * 32 + (cp & ~7) + (w >> 1) + 4 * (w & 1);
            g_w2[j] = f2tf32(W2[k * 128 + col]);
        }
    }
}

// ---------------- 1-ring mean pool (reference reshape scramble), tf32, permuted out -------
// 16 nodes per block, 16 threads per node, float4 gathers (MLP=7 per thread).
__global__ void __launch_bounds__(256) pool_kernel(const float* __restrict__ x) {
    __shared__ float sh[16][448];
    __shared__ int   srow[16][7];
    const int tid  = threadIdx.x;
    const int slot = tid >> 4;
    const int q    = tid & 15;
    const int node0 = blockIdx.x * 16;

    if (tid < 112) {
        int s = tid / 7, j = tid % 7;
        int node = node0 + s;
        srow[s][j] = (node < N_OUT) ? g_pool[node * 7 + j] : 0;
    }
    __syncthreads();
#pragma unroll
    for (int j = 0; j < 7; j++) {
        const float4 v = *((const float4*)(x + (size_t)srow[slot][j] * 64) + q);
        *(float4*)&sh[slot][j * 64 + q * 4] = v;
    }
    __syncthreads();

    const int node = node0 + slot;
    if (node < N_OUT) {
#pragma unroll
        for (int p = 0; p < 4; p++) {
            int c = q + 16 * p;
            float s = 0.f;
#pragma unroll
            for (int k = 0; k < 7; k++) s += sh[slot][c * 7 + k];
            g_pooled[(size_t)node * 64 + perm8(c)] = f2tf32(s * (1.0f / 7.0f));
        }
    }
}

// ---------------- gather-fused TF32 GEMM, cp.async 2-stage, paired-fragment layout --------
// BM=128, BN=128, BK=32.  8 warps in 4(M) x 2(N), warp tile 32x64.
// A smem [m][k'] stride 40, B smem [col][k'] stride 40; fragment pairs are float2.
// in: channel-pair-permuted; W: [ktile][col][k'] permuted.  out/t: normal order.
template <int C>
__global__ void __launch_bounds__(256, 2) gather_gemm_tf32(
    const float* __restrict__ in, const int* __restrict__ neigh,
    const float* __restrict__ W, const float* __restrict__ bias,
    float* __restrict__ out, float* __restrict__ part)
{
    constexpr int K   = 7 * C;
    constexpr int NT  = K / 32;
    constexpr int ASZ = 128 * 40;
    constexpr int BSZ = 128 * 40;
    constexpr int STG = ASZ + BSZ;

    extern __shared__ float smem[];          // 2 * STG floats
    __shared__ int   rows[128 * 7];
    __shared__ float red_s[4][128];
    __shared__ float red_q[4][128];

    const int tid  = threadIdx.x;
    const int m0   = blockIdx.x * 128;
    const int lane = tid & 31;
    const int wid  = tid >> 5;
    const int wm   = (wid & 3) * 32;
    const int wn   = (wid >> 2) * 64;
    const int g    = lane >> 2;
    const int tig  = lane & 3;

    for (int i = tid; i < 128 * 7; i += 256) {
        int node = m0 + (i / 7);
        rows[i] = (node < N_OUT) ? neigh[node * 7 + (i % 7)] : 0;
    }
    __syncthreads();

    auto issue = [&](int t) {
        const int k0 = t * 32;
        const int j  = k0 / C;
        const int c0 = k0 % C;
        float* dstA = smem + (t & 1) * STG;
        float* dstB = dstA + ASZ;
#pragma unroll
        for (int p = 0; p < 4; p++) {       // A: 128 rows x 32 k' = 1024 float4
            int q  = tid + p * 256;
            int m  = q >> 3;
            int kv = (q & 7) << 2;
            cp16(&dstA[m * 40 + kv], &in[(size_t)rows[m * 7 + j] * C + c0 + kv]);
        }
#pragma unroll
        for (int p = 0; p < 4; p++) {       // B: 128 cols x 32 k' = 1024 float4
            int q   = tid + p * 256;
            int col = q >> 3;
            int kv  = (q & 7) << 2;
            cp16(&dstB[col * 40 + kv], &W[(size_t)t * 4096 + col * 32 + kv]);
        }
        cp_commit();
    };

    issue(0);
    issue(1);

    float acc[2][8][4];
#pragma unroll
    for (int mt = 0; mt < 2; mt++)
#pragma unroll
        for (int nt = 0; nt < 8; nt++)
#pragma unroll
            for (int i = 0; i < 4; i++) acc[mt][nt][i] = 0.f;

    for (int t = 0; t < NT; t++) {
        if (t < NT - 1) cp_wait<1>(); else cp_wait<0>();
        __syncthreads();

        const float* Ab = smem + (t & 1) * STG;
        const float* Bb = Ab + ASZ;
#pragma unroll
        for (int kk = 0; kk < 4; kk++) {
            const int kb = kk * 8 + 2 * tig;
            uint32_t a[2][4];
#pragma unroll
            for (int mt = 0; mt < 2; mt++) {
                int r = wm + mt * 16 + g;
                float2 f0 = *(const float2*)&Ab[r * 40 + kb];
                float2 f1 = *(const float2*)&Ab[(r + 8) * 40 + kb];
                a[mt][0] = __float_as_uint(f0.x);
                a[mt][1] = __float_as_uint(f1.x);
                a[mt][2] = __float_as_uint(f0.y);
                a[mt][3] = __float_as_uint(f1.y);
            }
            uint32_t b[8][2];
#pragma unroll
            for (int nt = 0; nt < 8; nt++) {
                int col = wn + nt * 8 + g;
                float2 f = *(const float2*)&Bb[col * 40 + kb];
                b[nt][0] = __float_as_uint(f.x);
                b[nt][1] = __float_as_uint(f.y);
            }
#pragma unroll
            for (int mt = 0; mt < 2; mt++)
#pragma unroll
                for (int nt = 0; nt < 8; nt++)
                    mma_tf32(acc[mt][nt], a[mt], b[nt]);
        }
        __syncthreads();
        if (t + 2 < NT) issue(t + 2);
    }

    // ---- epilogue: bias, store, per-column sum/sumsq (valid rows only) ----
    float cs[16], cq[16];
#pragma unroll
    for (int i = 0; i < 16; i++) { cs[i] = 0.f; cq[i] = 0.f; }

#pragma unroll
    for (int mt = 0; mt < 2; mt++) {
        int r0 = m0 + wm + mt * 16 + g;
        bool v0 = r0 < N_OUT, v1 = (r0 + 8) < N_OUT;
#pragma unroll
        for (int nt = 0; nt < 8; nt++) {
            int col = wn + nt * 8 + 2 * tig;
            float2 bv = *(const float2*)&bias[col];
            float o00 = acc[mt][nt][0] + bv.x, o01 = acc[mt][nt][1] + bv.y;
            float o10 = acc[mt][nt][2] + bv.x, o11 = acc[mt][nt][3] + bv.y;
            if (v0) {
                *(float2*)&out[(size_t)r0 * OUTC + col] = make_float2(o00, o01);
                cs[nt*2]   += o00; cq[nt*2]   += o00 * o00;
                cs[nt*2+1] += o01; cq[nt*2+1] += o01 * o01;
            }
            if (v1) {
                *(float2*)&out[(size_t)(r0 + 8) * OUTC + col] = make_float2(o10, o11);
                cs[nt*2]   += o10; cq[nt*2]   += o10 * o10;
                cs[nt*2+1] += o11; cq[nt*2+1] += o11 * o11;
            }
        }
    }
#pragma unroll
    for (int i = 0; i < 16; i++) {
#pragma unroll
        for (int d = 4; d < 32; d <<= 1) {
            cs[i] += __shfl_xor_sync(0xffffffffu, cs[i], d);
            cq[i] += __shfl_xor_sync(0xffffffffu, cq[i], d);
        }
    }
    if (lane < 4) {   // g == 0, tig = lane; warps sharing (wid&3) differ in wn -> disjoint cols
#pragma unroll
        for (int nt = 0; nt < 8; nt++) {
            int col = wn + nt * 8 + 2 * lane;
            red_s[wid & 3][col]     = cs[nt*2];
            red_s[wid & 3][col + 1] = cs[nt*2+1];
            red_q[wid & 3][col]     = cq[nt*2];
            red_q[wid & 3][col + 1] = cq[nt*2+1];
        }
    }
    __syncthreads();
    if (tid < 128) {
        float s = red_s[0][tid] + red_s[1][tid] + red_s[2][tid] + red_s[3][tid];
        float q = red_q[0][tid] + red_q[1][tid] + red_q[2][tid] + red_q[3][tid];
        part[blockIdx.x * 256 + tid]       = s;
        part[blockIdx.x * 256 + 128 + tid] = q;
    }
}

// ---------------- BN finalize + apply ----------------
__global__ void finalize_kernel(const float* __restrict__ gamma,
                                const float* __restrict__ beta, int n_rows) {
    const int ch = threadIdx.x;  // 128 threads
    float s = 0.f, ss = 0.f;
#pragma unroll 4
    for (int b = 0; b < GEMM_GRID; b++) {
        s  += g_part[b * 256 + ch];
        ss += g_part[b * 256 + 128 + ch];
    }
    float m  = s / n_rows;
    float v  = ss / n_rows - m * m;          // biased variance
    float r  = rsqrtf(v + 1e-5f);
    float sc = r * gamma[ch];
    g_bnp[ch]       = sc;
    g_bnp[128 + ch] = beta[ch] - m * sc;
}

// PERMOUT: write tf32-rounded result at pair-permuted channel position (for next GEMM).
template <bool PERMOUT>
__global__ void bn_kernel(const float* __restrict__ t, float* __restrict__ out, int n_rows) {
    __shared__ float sc[128], sb[128];
    if (threadIdx.x < 128) {
        sc[threadIdx.x] = g_bnp[threadIdx.x];
        sb[threadIdx.x] = g_bnp[128 + threadIdx.x];
    }
    __syncthreads();
    const int total = n_rows * OUTC;
    for (int i = blockIdx.x * blockDim.x + threadIdx.x; i < total;
         i += gridDim.x * blockDim.x) {
        int ch = i & 127;
        float y = t[i] * sc[ch] + sb[ch];
        y = (y >= 0.f) ? y : 0.2f * y;
        if (PERMOUT) out[(i & ~127) | perm8(ch)] = f2tf32(y);
        else         out[i] = y;
    }
}

// ---------------- launch ----------------
extern "C" void kernel_launch(void* const* d_in, const int* in_sizes, int n_in,
                              void* d_out, int out_size) {
    const float* x    = (const float*)d_in[0];
    const int*   nraw = (const int*)d_in[1];
    const int*   praw = (const int*)d_in[2];
    const float* W1   = (const float*)d_in[3];
    const float* b1   = (const float*)d_in[4];
    const float* g1   = (const float*)d_in[5];
    const float* be1  = (const float*)d_in[6];
    const float* W2   = (const float*)d_in[7];
    const float* b2   = (const float*)d_in[8];
    const float* g2   = (const float*)d_in[9];
    const float* be2  = (const float*)d_in[10];
    float* out = (float*)d_out;

    int *p_neigh, *p_pool;
    float *p_pooled, *p_t1, *p_h, *p_t2, *p_w1, *p_w2, *p_part;
    cudaGetSymbolAddress((void**)&p_neigh,  g_neigh);
    cudaGetSymbolAddress((void**)&p_pool,   g_pool);
    cudaGetSymbolAddress((void**)&p_pooled, g_pooled);
    cudaGetSymbolAddress((void**)&p_t1,     g_t1);
    cudaGetSymbolAddress((void**)&p_h,      g_h);
    cudaGetSymbolAddress((void**)&p_t2,     g_t2);
    cudaGetSymbolAddress((void**)&p_w1,     g_w1);
    cudaGetSymbolAddress((void**)&p_w2,     g_w2);
    cudaGetSymbolAddress((void**)&p_part,   g_part);

    const int SMEM_DYN = 2 * (128 * 40 + 128 * 40) * (int)sizeof(float);  // 81920
    cudaFuncSetAttribute(gather_gemm_tf32<64>,
                         cudaFuncAttributeMaxDynamicSharedMemorySize, SMEM_DYN);
    cudaFuncSetAttribute(gather_gemm_tf32<128>,
                         cudaFuncAttributeMaxDynamicSharedMemorySize, SMEM_DYN);

    convert_idx2_kernel<<<224, 256>>>(nraw, p_neigh, praw, p_pool, NIDX);
    wconv_kernel<<<(14 * 4096 + 28 * 4096 + 255) / 256, 256>>>(W1, W2);

    pool_kernel<<<(N_OUT + 15) / 16, 256>>>(x);

    gather_gemm_tf32<64><<<GEMM_GRID, 256, SMEM_DYN>>>(p_pooled, p_neigh, p_w1, b1, p_t1, p_part);
    finalize_kernel<<<1, 128>>>(g1, be1, N_OUT);
    bn_kernel<true><<<512, 256>>>(p_t1, p_h, N_OUT);

    gather_gemm_tf32<128><<<GEMM_GRID, 256, SMEM_DYN>>>(p_h, p_neigh, p_w2, b2, p_t2, p_part);
    finalize_kernel<<<1, 128>>>(g2, be2, N_OUT);
    bn_kernel<false><<<512, 256>>>(p_t2, out, N_OUT);
}

// round 8
// speedup vs baseline: 1.1525x; 1.0085x over previous
#include <cuda_runtime.h>
#include <cstdint>

static constexpr int N_OUT = 40962;
static constexpr int NIDX  = N_OUT * 7;          // 286734
static constexpr int OUTC  = 128;
static constexpr int GEMM_GRID = (N_OUT + 127) / 128;   // 321

// ---------------- device scratch (no allocations allowed) ----------------
__device__ int   g_neigh[NIDX];
__device__ int   g_pool[NIDX];
__device__ float g_pooled[(size_t)N_OUT * 64];
__device__ float g_t1[(size_t)N_OUT * OUTC];
__device__ float g_h [(size_t)N_OUT * OUTC];
__device__ float g_t2[(size_t)N_OUT * OUTC];
__device__ float g_w1[448 * 128];
__device__ float g_w2[896 * 128];
__device__ float g_part[GEMM_GRID * 256];        // per-GEMM-block partial sum/sumsq
__device__ float g_bnp[256];                     // scale (0..127), shift (128..255)

// ---------------- helpers ----------------
__device__ __forceinline__ float f2tf32(float x) {
    uint32_t r;
    asm("cvt.rna.tf32.f32 %0, %1;" : "=r"(r) : "f"(x));
    return __uint_as_float(r);
}
__device__ __forceinline__ void mma_tf32(float* d, const uint32_t* a, const uint32_t* b) {
    asm volatile(
        "mma.sync.aligned.m16n8k8.row.col.f32.tf32.tf32.f32 "
        "{%0,%1,%2,%3}, {%4,%5,%6,%7}, {%8,%9}, {%0,%1,%2,%3};\n"
        : "+f"(d[0]), "+f"(d[1]), "+f"(d[2]), "+f"(d[3])
        : "r"(a[0]), "r"(a[1]), "r"(a[2]), "r"(a[3]), "r"(b[0]), "r"(b[1]));
}
__device__ __forceinline__ void cp16(float* smem_dst, const float* gsrc) {
    uint32_t s = (uint32_t)__cvta_generic_to_shared(smem_dst);
    asm volatile("cp.async.cg.shared.global [%0], [%1], 16;\n" :: "r"(s), "l"(gsrc));
}
__device__ __forceinline__ void cp_commit() { asm volatile("cp.async.commit_group;\n"); }
template <int N>
__device__ __forceinline__ void cp_wait() { asm volatile("cp.async.wait_group %0;\n" :: "n"(N)); }

// ---------------- index dtype detect + convert (both arrays, one launch) ----------------
__global__ void convert_idx2_kernel(const int* __restrict__ rawA, int* __restrict__ outA,
                                    const int* __restrict__ rawB, int* __restrict__ outB, int n) {
    const int half = gridDim.x / 2;
    const int* raw = (blockIdx.x < half) ? rawA : rawB;
    int*       out = (blockIdx.x < half) ? outA : outB;
    const int  b   = (blockIdx.x < half) ? blockIdx.x : blockIdx.x - half;
    __shared__ int s_is64;
    if (threadIdx.x == 0) s_is64 = 1;
    __syncthreads();
    for (int i = threadIdx.x; i < 1024; i += blockDim.x)
        if (raw[2 * i + 1] != 0) s_is64 = 0;
    __syncthreads();
    const int f = s_is64;
    for (int i = b * blockDim.x + threadIdx.x; i < n; i += half * blockDim.x)
        out[i] = f ? raw[2 * i] : raw[i];
}

// ---------------- weights -> tf32 ----------------
__global__ void wconv_kernel(const float* __restrict__ W1, const float* __restrict__ W2) {
    int i = blockIdx.x * blockDim.x + threadIdx.x;
    if (i < 448 * 128) g_w1[i] = f2tf32(W1[i]);
    else { int j = i - 448 * 128; if (j < 896 * 128) g_w2[j] = f2tf32(W2[j]); }
}

// ---------------- 1-ring mean pool (reference reshape scramble), tf32 output ----------------
// 16 nodes per block, 16 threads per node, float4 gathers (MLP=7 per thread).
__global__ void __launch_bounds__(256) pool_kernel(const float* __restrict__ x) {
    __shared__ float sh[16][448];
    __shared__ int   srow[16][7];
    const int tid  = threadIdx.x;
    const int slot = tid >> 4;
    const int q    = tid & 15;
    const int node0 = blockIdx.x * 16;

    if (tid < 112) {
        int s = tid / 7, j = tid % 7;
        int node = node0 + s;
        srow[s][j] = (node < N_OUT) ? g_pool[node * 7 + j] : 0;
    }
    __syncthreads();
#pragma unroll
    for (int j = 0; j < 7; j++) {
        const float4 v = *((const float4*)(x + (size_t)srow[slot][j] * 64) + q);
        *(float4*)&sh[slot][j * 64 + q * 4] = v;
    }
    __syncthreads();

    const int node = node0 + slot;
    if (node < N_OUT) {
#pragma unroll
        for (int p = 0; p < 4; p++) {
            int c = q + 16 * p;
            float s = 0.f;
#pragma unroll
            for (int k = 0; k < 7; k++) s += sh[slot][c * 7 + k];
            g_pooled[(size_t)node * 64 + c] = f2tf32(s * (1.0f / 7.0f));
        }
    }
}

// ---------------- gather-fused TF32 GEMM, 3-buffer cp.async, 1 sync/iter ----------------
// out[M,128] = gather(in)[M,7C] @ W[7C,128] + bias; per-block sum/sumsq -> part.
// BM=128, BN=128, BK=32; 8 warps 4(M)x2(N), warp tile 32x64. in/W pre-rounded tf32.
template <int C>
__global__ void __launch_bounds__(256, 2) gather_gemm_tf32(
    const float* __restrict__ in, const int* __restrict__ neigh,
    const float* __restrict__ W, const float* __restrict__ bias,
    float* __restrict__ out, float* __restrict__ part)
{
    constexpr int K   = 7 * C;
    constexpr int NT  = K / 32;
    constexpr int ASZ = 128 * 36;
    constexpr int BSZ = 32 * 136;
    constexpr int STG = ASZ + BSZ;

    extern __shared__ float smem[];          // 3 * STG floats
    __shared__ int   rows[128 * 7];
    __shared__ float red_s[4][128];
    __shared__ float red_q[4][128];

    const int tid  = threadIdx.x;
    const int m0   = blockIdx.x * 128;
    const int lane = tid & 31;
    const int wid  = tid >> 5;
    const int wm   = (wid & 3) * 32;
    const int wn   = (wid >> 2) * 64;
    const int g    = lane >> 2;
    const int tig  = lane & 3;

    for (int i = tid; i < 128 * 7; i += 256) {
        int node = m0 + (i / 7);
        rows[i] = (node < N_OUT) ? neigh[node * 7 + (i % 7)] : 0;
    }
    __syncthreads();

    auto issue = [&](int t) {
        const int k0 = t * 32;
        const int j  = k0 / C;
        const int c0 = k0 % C;
        float* dstA = smem + (t % 3) * STG;
        float* dstB = dstA + ASZ;
#pragma unroll
        for (int p = 0; p < 4; p++) {
            int q  = tid + p * 256;
            int m  = q >> 3;
            int kv = (q & 7) << 2;
            cp16(&dstA[m * 36 + kv], &in[(size_t)rows[m * 7 + j] * C + c0 + kv]);
        }
#pragma unroll
        for (int p = 0; p < 4; p++) {
            int q   = tid + p * 256;
            int kl  = q >> 5;
            int col = (q & 31) << 2;
            cp16(&dstB[kl * 136 + col], &W[(size_t)(k0 + kl) * 128 + col]);
        }
        cp_commit();
    };

    issue(0);
    issue(1);

    float acc[2][8][4];
#pragma unroll
    for (int mt = 0; mt < 2; mt++)
#pragma unroll
        for (int nt = 0; nt < 8; nt++)
#pragma unroll
            for (int i = 0; i < 4; i++) acc[mt][nt][i] = 0.f;

    for (int t = 0; t < NT; t++) {
        if (t + 1 < NT) cp_wait<1>(); else cp_wait<0>();
        __syncthreads();
        // prefetch t+2 into buffer (t+2)%3 == (t-1)%3: its tile-(t-1) readers all
        // passed the sync above, so the buffer is free. Overlaps with MMAs below.
        if (t + 2 < NT) issue(t + 2);

        const float* Ab = smem + (t % 3) * STG;
        const float* Bb = Ab + ASZ;
#pragma unroll
        for (int kk = 0; kk < 4; kk++) {
            const int kb = kk * 8;
            uint32_t a[2][4];
#pragma unroll
            for (int mt = 0; mt < 2; mt++) {
                int r = wm + mt * 16 + g;
                a[mt][0] = __float_as_uint(Ab[r * 36 + kb + tig]);
                a[mt][1] = __float_as_uint(Ab[(r + 8) * 36 + kb + tig]);
                a[mt][2] = __float_as_uint(Ab[r * 36 + kb + tig + 4]);
                a[mt][3] = __float_as_uint(Ab[(r + 8) * 36 + kb + tig + 4]);
            }
            uint32_t b[8][2];
#pragma unroll
            for (int nt = 0; nt < 8; nt++) {
                b[nt][0] = __float_as_uint(Bb[(kb + tig) * 136 + wn + nt * 8 + g]);
                b[nt][1] = __float_as_uint(Bb[(kb + tig + 4) * 136 + wn + nt * 8 + g]);
            }
#pragma unroll
            for (int mt = 0; mt < 2; mt++)
#pragma unroll
                for (int nt = 0; nt < 8; nt++)
                    mma_tf32(acc[mt][nt], a[mt], b[nt]);
        }
    }

    // ---- epilogue: bias, store, per-column sum/sumsq (valid rows only) ----
    float cs[16], cq[16];
#pragma unroll
    for (int i = 0; i < 16; i++) { cs[i] = 0.f; cq[i] = 0.f; }

#pragma unroll
    for (int mt = 0; mt < 2; mt++) {
        int r0 = m0 + wm + mt * 16 + g;
        bool v0 = r0 < N_OUT, v1 = (r0 + 8) < N_OUT;
#pragma unroll
        for (int nt = 0; nt < 8; nt++) {
            int col = wn + nt * 8 + 2 * tig;
            float2 bv = *(const float2*)&bias[col];
            float o00 = acc[mt][nt][0] + bv.x, o01 = acc[mt][nt][1] + bv.y;
            float o10 = acc[mt][nt][2] + bv.x, o11 = acc[mt][nt][3] + bv.y;
            if (v0) {
                *(float2*)&out[(size_t)r0 * OUTC + col] = make_float2(o00, o01);
                cs[nt*2]   += o00; cq[nt*2]   += o00 * o00;
                cs[nt*2+1] += o01; cq[nt*2+1] += o01 * o01;
            }
            if (v1) {
                *(float2*)&out[(size_t)(r0 + 8) * OUTC + col] = make_float2(o10, o11);
                cs[nt*2]   += o10; cq[nt*2]   += o10 * o10;
                cs[nt*2+1] += o11; cq[nt*2+1] += o11 * o11;
            }
        }
    }
#pragma unroll
    for (int i = 0; i < 16; i++) {
#pragma unroll
        for (int d = 4; d < 32; d <<= 1) {
            cs[i] += __shfl_xor_sync(0xffffffffu, cs[i], d);
            cq[i] += __shfl_xor_sync(0xffffffffu, cq[i], d);
        }
    }
    if (lane < 4) {   // g == 0, tig = lane; warps sharing (wid&3) differ in wn -> disjoint cols
#pragma unroll
        for (int nt = 0; nt < 8; nt++) {
            int col = wn + nt * 8 + 2 * lane;
            red_s[wid & 3][col]     = cs[nt*2];
            red_s[wid & 3][col + 1] = cs[nt*2+1];
            red_q[wid & 3][col]     = cq[nt*2];
            red_q[wid & 3][col + 1] = cq[nt*2+1];
        }
    }
    __syncthreads();
    if (tid < 128) {
        float s = red_s[0][tid] + red_s[1][tid] + red_s[2][tid] + red_s[3][tid];
        float q = red_q[0][tid] + red_q[1][tid] + red_q[2][tid] + red_q[3][tid];
        part[blockIdx.x * 256 + tid]       = s;
        part[blockIdx.x * 256 + 128 + tid] = q;
    }
}

// ---------------- BN finalize + apply ----------------
__global__ void finalize_kernel(const float* __restrict__ gamma,
                                const float* __restrict__ beta, int n_rows) {
    const int ch = threadIdx.x;  // 128 threads
    float s = 0.f, ss = 0.f;
#pragma unroll 4
    for (int b = 0; b < GEMM_GRID; b++) {
        s  += g_part[b * 256 + ch];
        ss += g_part[b * 256 + 128 + ch];
    }
    float m  = s / n_rows;
    float v  = ss / n_rows - m * m;          // biased variance
    float r  = rsqrtf(v + 1e-5f);
    float sc = r * gamma[ch];
    g_bnp[ch]       = sc;
    g_bnp[128 + ch] = beta[ch] - m * sc;
}

template <bool CVT>
__global__ void bn_kernel(const float* __restrict__ t, float* __restrict__ out, int n_rows) {
    __shared__ float sc[128], sb[128];
    if (threadIdx.x < 128) {
        sc[threadIdx.x] = g_bnp[threadIdx.x];
        sb[threadIdx.x] = g_bnp[128 + threadIdx.x];
    }
    __syncthreads();
    const int total = n_rows * OUTC;
    for (int i = blockIdx.x * blockDim.x + threadIdx.x; i < total;
         i += gridDim.x * blockDim.x) {
        float y = t[i] * sc[i & 127] + sb[i & 127];
        y = (y >= 0.f) ? y : 0.2f * y;
        out[i] = CVT ? f2tf32(y) : y;
    }
}

// ---------------- launch ----------------
extern "C" void kernel_launch(void* const* d_in, const int* in_sizes, int n_in,
                              void* d_out, int out_size) {
    const float* x    = (const float*)d_in[0];
    const int*   nraw = (const int*)d_in[1];
    const int*   praw = (const int*)d_in[2];
    const float* W1   = (const float*)d_in[3];
    const float* b1   = (const float*)d_in[4];
    const float* g1   = (const float*)d_in[5];
    const float* be1  = (const float*)d_in[6];
    const float* W2   = (const float*)d_in[7];
    const float* b2   = (const float*)d_in[8];
    const float* g2   = (const float*)d_in[9];
    const float* be2  = (const float*)d_in[10];
    float* out = (float*)d_out;

    int *p_neigh, *p_pool;
    float *p_pooled, *p_t1, *p_h, *p_t2, *p_w1, *p_w2, *p_part;
    cudaGetSymbolAddress((void**)&p_neigh,  g_neigh);
    cudaGetSymbolAddress((void**)&p_pool,   g_pool);
    cudaGetSymbolAddress((void**)&p_pooled, g_pooled);
    cudaGetSymbolAddress((void**)&p_t1,     g_t1);
    cudaGetSymbolAddress((void**)&p_h,      g_h);
    cudaGetSymbolAddress((void**)&p_t2,     g_t2);
    cudaGetSymbolAddress((void**)&p_w1,     g_w1);
    cudaGetSymbolAddress((void**)&p_w2,     g_w2);
    cudaGetSymbolAddress((void**)&p_part,   g_part);

    const int SMEM_DYN = 3 * (128 * 36 + 32 * 136) * (int)sizeof(float);  // 107520
    cudaFuncSetAttribute(gather_gemm_tf32<64>,
                         cudaFuncAttributeMaxDynamicSharedMemorySize, SMEM_DYN);
    cudaFuncSetAttribute(gather_gemm_tf32<128>,
                         cudaFuncAttributeMaxDynamicSharedMemorySize, SMEM_DYN);

    convert_idx2_kernel<<<224, 256>>>(nraw, p_neigh, praw, p_pool, NIDX);
    wconv_kernel<<<(448 * 128 + 896 * 128 + 255) / 256, 256>>>(W1, W2);

    pool_kernel<<<(N_OUT + 15) / 16, 256>>>(x);

    gather_gemm_tf32<64><<<GEMM_GRID, 256, SMEM_DYN>>>(p_pooled, p_neigh, p_w1, b1, p_t1, p_part);
    finalize_kernel<<<1, 128>>>(g1, be1, N_OUT);
    bn_kernel<true><<<512, 256>>>(p_t1, p_h, N_OUT);

    gather_gemm_tf32<128><<<GEMM_GRID, 256, SMEM_DYN>>>(p_h, p_neigh, p_w2, b2, p_t2, p_part);
    finalize_kernel<<<1, 128>>>(g2, be2, N_OUT);
    bn_kernel<false><<<512, 256>>>(p_t2, out, N_OUT);
}

// round 10
// speedup vs baseline: 1.1922x; 1.0345x over previous
#include <cuda_runtime.h>
#include <cstdint>

static constexpr int N_OUT = 40962;
static constexpr int NIDX  = N_OUT * 7;          // 286734
static constexpr int OUTC  = 128;
static constexpr int GEMM_GRID = (N_OUT + 127) / 128;   // 321

// ---------------- device scratch (no allocations allowed) ----------------
__device__ int   g_neigh[NIDX];
__device__ int   g_pool[NIDX];
__device__ float g_pooled[(size_t)N_OUT * 64];
__device__ float g_t1[(size_t)N_OUT * OUTC];
__device__ float g_h [(size_t)N_OUT * OUTC];
__device__ float g_t2[(size_t)N_OUT * OUTC];
__device__ float g_w1[448 * 128];
__device__ float g_w2[896 * 128];
__device__ float g_part[GEMM_GRID * 256];        // per-GEMM-block partial sum/sumsq
__device__ float g_bnp[256];                     // scale (0..127), shift (128..255)

// ---------------- helpers ----------------
__device__ __forceinline__ float f2tf32(float x) {
    uint32_t r;
    asm("cvt.rna.tf32.f32 %0, %1;" : "=r"(r) : "f"(x));
    return __uint_as_float(r);
}
__device__ __forceinline__ void mma_tf32(float* d, const uint32_t* a, const uint32_t* b) {
    asm volatile(
        "mma.sync.aligned.m16n8k8.row.col.f32.tf32.tf32.f32 "
        "{%0,%1,%2,%3}, {%4,%5,%6,%7}, {%8,%9}, {%0,%1,%2,%3};\n"
        : "+f"(d[0]), "+f"(d[1]), "+f"(d[2]), "+f"(d[3])
        : "r"(a[0]), "r"(a[1]), "r"(a[2]), "r"(a[3]), "r"(b[0]), "r"(b[1]));
}
__device__ __forceinline__ void cp16(float* smem_dst, const float* gsrc) {
    uint32_t s = (uint32_t)__cvta_generic_to_shared(smem_dst);
    asm volatile("cp.async.cg.shared.global [%0], [%1], 16;\n" :: "r"(s), "l"(gsrc));
}
__device__ __forceinline__ void cp_commit() { asm volatile("cp.async.commit_group;\n"); }
template <int N>
__device__ __forceinline__ void cp_wait() { asm volatile("cp.async.wait_group %0;\n" :: "n"(N)); }

// ---------------- index dtype detect + convert ----------------
__global__ void convert_idx_kernel(const int* __restrict__ raw, int* __restrict__ out, int n) {
    __shared__ int s_is64;
    if (threadIdx.x == 0) s_is64 = 1;
    __syncthreads();
    for (int i = threadIdx.x; i < 1024; i += blockDim.x)
        if (raw[2 * i + 1] != 0) s_is64 = 0;
    __syncthreads();
    const int f = s_is64;
    for (int i = blockIdx.x * blockDim.x + threadIdx.x; i < n; i += gridDim.x * blockDim.x)
        out[i] = f ? raw[2 * i] : raw[i];
}

// ---------------- weights -> tf32 ----------------
__global__ void wconv_kernel(const float* __restrict__ W1, const float* __restrict__ W2) {
    int i = blockIdx.x * blockDim.x + threadIdx.x;
    if (i < 448 * 128) g_w1[i] = f2tf32(W1[i]);
    else { int j = i - 448 * 128; if (j < 896 * 128) g_w2[j] = f2tf32(W2[j]); }
}

// ---------------- 1-ring mean pool (reference reshape scramble), tf32 output ----------------
// 16 nodes per block, 16 threads per node, float4 gathers (MLP=7 per thread).
__global__ void __launch_bounds__(256) pool_kernel(const float* __restrict__ x) {
    __shared__ float sh[16][448];
    __shared__ int   srow[16][7];
    const int tid  = threadIdx.x;
    const int slot = tid >> 4;
    const int q    = tid & 15;
    const int node0 = blockIdx.x * 16;

    if (tid < 112) {
        int s = tid / 7, j = tid % 7;
        int node = node0 + s;
        srow[s][j] = (node < N_OUT) ? g_pool[node * 7 + j] : 0;
    }
    __syncthreads();
#pragma unroll
    for (int j = 0; j < 7; j++) {
        const float4 v = *((const float4*)(x + (size_t)srow[slot][j] * 64) + q);
        *(float4*)&sh[slot][j * 64 + q * 4] = v;
    }
    __syncthreads();

    const int node = node0 + slot;
    if (node < N_OUT) {
#pragma unroll
        for (int p = 0; p < 4; p++) {
            int c = q + 16 * p;
            float s = 0.f;
#pragma unroll
            for (int k = 0; k < 7; k++) s += sh[slot][c * 7 + k];
            g_pooled[(size_t)node * 64 + c] = f2tf32(s * (1.0f / 7.0f));
        }
    }
}

// ---------------- gather-fused TF32 GEMM, cp.async 2-stage, fused BN partials ----------------
// out[M,128] = gather(in)[M,7C] @ W[7C,128] + bias; per-block channel sum/sumsq -> g_part.
// in and W must be pre-rounded to tf32. BM=128, BN=128, BK=32; 8 warps 4(M)x2(N).
template <int C>
__global__ void __launch_bounds__(256, 2) gather_gemm_tf32(
    const float* __restrict__ in, const int* __restrict__ neigh,
    const float* __restrict__ W, const float* __restrict__ bias,
    float* __restrict__ out, float* __restrict__ part)
{
    constexpr int K   = 7 * C;
    constexpr int NT  = K / 32;
    constexpr int ASZ = 128 * 36;
    constexpr int BSZ = 32 * 136;
    constexpr int STG = ASZ + BSZ;

    extern __shared__ float smem[];          // 2 * STG floats
    __shared__ int   rows[128 * 7];
    __shared__ float red_s[4][128];
    __shared__ float red_q[4][128];

    const int tid  = threadIdx.x;
    const int m0   = blockIdx.x * 128;
    const int lane = tid & 31;
    const int wid  = tid >> 5;
    const int wm   = (wid & 3) * 32;
    const int wn   = (wid >> 2) * 64;
    const int g    = lane >> 2;
    const int tig  = lane & 3;

    for (int i = tid; i < 128 * 7; i += 256) {
        int node = m0 + (i / 7);
        rows[i] = (node < N_OUT) ? neigh[node * 7 + (i % 7)] : 0;
    }
    __syncthreads();

    auto issue = [&](int t) {
        const int k0 = t * 32;
        const int j  = k0 / C;
        const int c0 = k0 % C;
        float* dstA = smem + (t & 1) * STG;
        float* dstB = dstA + ASZ;
#pragma unroll
        for (int p = 0; p < 4; p++) {
            int q  = tid + p * 256;
            int m  = q >> 3;
            int kv = (q & 7) << 2;
            cp16(&dstA[m * 36 + kv], &in[(size_t)rows[m * 7 + j] * C + c0 + kv]);
        }
#pragma unroll
        for (int p = 0; p < 4; p++) {
            int q   = tid + p * 256;
            int kl  = q >> 5;
            int col = (q & 31) << 2;
            cp16(&dstB[kl * 136 + col], &W[(size_t)(k0 + kl) * 128 + col]);
        }
        cp_commit();
    };

    issue(0);
    issue(1);

    float acc[2][8][4];
#pragma unroll
    for (int mt = 0; mt < 2; mt++)
#pragma unroll
        for (int nt = 0; nt < 8; nt++)
#pragma unroll
            for (int i = 0; i < 4; i++) acc[mt][nt][i] = 0.f;

    for (int t = 0; t < NT; t++) {
        if (t < NT - 1) cp_wait<1>(); else cp_wait<0>();
        __syncthreads();

        const float* Ab = smem + (t & 1) * STG;
        const float* Bb = Ab + ASZ;
#pragma unroll
        for (int kk = 0; kk < 4; kk++) {
            const int kb = kk * 8;
            uint32_t a[2][4];
#pragma unroll
            for (int mt = 0; mt < 2; mt++) {
                int r = wm + mt * 16 + g;
                a[mt][0] = __float_as_uint(Ab[r * 36 + kb + tig]);
                a[mt][1] = __float_as_uint(Ab[(r + 8) * 36 + kb + tig]);
                a[mt][2] = __float_as_uint(Ab[r * 36 + kb + tig + 4]);
                a[mt][3] = __float_as_uint(Ab[(r + 8) * 36 + kb + tig + 4]);
            }
            uint32_t b[8][2];
#pragma unroll
            for (int nt = 0; nt < 8; nt++) {
                b[nt][0] = __float_as_uint(Bb[(kb + tig) * 136 + wn + nt * 8 + g]);
                b[nt][1] = __float_as_uint(Bb[(kb + tig + 4) * 136 + wn + nt * 8 + g]);
            }
#pragma unroll
            for (int mt = 0; mt < 2; mt++)
#pragma unroll
                for (int nt = 0; nt < 8; nt++)
                    mma_tf32(acc[mt][nt], a[mt], b[nt]);
        }
        __syncthreads();
        if (t + 2 < NT) issue(t + 2);
    }

    // ---- epilogue: bias, store, per-column sum/sumsq (valid rows only) ----
    float cs[16], cq[16];
#pragma unroll
    for (int i = 0; i < 16; i++) { cs[i] = 0.f; cq[i] = 0.f; }

#pragma unroll
    for (int mt = 0; mt < 2; mt++) {
        int r0 = m0 + wm + mt * 16 + g;
        bool v0 = r0 < N_OUT, v1 = (r0 + 8) < N_OUT;
#pragma unroll
        for (int nt = 0; nt < 8; nt++) {
            int col = wn + nt * 8 + 2 * tig;
            float2 bv = *(const float2*)&bias[col];
            float o00 = acc[mt][nt][0] + bv.x, o01 = acc[mt][nt][1] + bv.y;
            float o10 = acc[mt][nt][2] + bv.x, o11 = acc[mt][nt][3] + bv.y;
            if (v0) {
                *(float2*)&out[(size_t)r0 * OUTC + col] = make_float2(o00, o01);
                cs[nt*2]   += o00; cq[nt*2]   += o00 * o00;
                cs[nt*2+1] += o01; cq[nt*2+1] += o01 * o01;
            }
            if (v1) {
                *(float2*)&out[(size_t)(r0 + 8) * OUTC + col] = make_float2(o10, o11);
                cs[nt*2]   += o10; cq[nt*2]   += o10 * o10;
                cs[nt*2+1] += o11; cq[nt*2+1] += o11 * o11;
            }
        }
    }
    // reduce over g (lanes xor 4,8,16 keep tig fixed)
#pragma unroll
    for (int i = 0; i < 16; i++) {
#pragma unroll
        for (int d = 4; d < 32; d <<= 1) {
            cs[i] += __shfl_xor_sync(0xffffffffu, cs[i], d);
            cq[i] += __shfl_xor_sync(0xffffffffu, cq[i], d);
        }
    }
    if (lane < 4) {   // g == 0, tig = lane
#pragma unroll
        for (int nt = 0; nt < 8; nt++) {
            int col = wn + nt * 8 + 2 * lane;
            red_s[wid & 3][col]     = cs[nt*2];
            red_s[wid & 3][col + 1] = cs[nt*2+1];
            red_q[wid & 3][col]     = cq[nt*2];
            red_q[wid & 3][col + 1] = cq[nt*2+1];
        }
    }
    __syncthreads();
    if (tid < 128) {
        float s = red_s[0][tid] + red_s[1][tid] + red_s[2][tid] + red_s[3][tid];
        float q = red_q[0][tid] + red_q[1][tid] + red_q[2][tid] + red_q[3][tid];
        part[blockIdx.x * 256 + tid]       = s;
        part[blockIdx.x * 256 + 128 + tid] = q;
    }
}

// ---------------- BN finalize + apply ----------------
__global__ void finalize_kernel(const float* __restrict__ gamma,
                                const float* __restrict__ beta, int n_rows) {
    const int ch = threadIdx.x;  // 128 threads
    float s = 0.f, ss = 0.f;
#pragma unroll 4
    for (int b = 0; b < GEMM_GRID; b++) {
        s  += g_part[b * 256 + ch];
        ss += g_part[b * 256 + 128 + ch];
    }
    float m  = s / n_rows;
    float v  = ss / n_rows - m * m;          // biased variance
    float r  = rsqrtf(v + 1e-5f);
    float sc = r * gamma[ch];
    g_bnp[ch]       = sc;
    g_bnp[128 + ch] = beta[ch] - m * sc;
}

// float4-vectorized BN apply + leaky; CVT: round to tf32 for the next GEMM's A operand.
template <bool CVT>
__global__ void bn_kernel(const float* __restrict__ t, float* __restrict__ out, int n_rows) {
    __shared__ float sc[128], sb[128];
    if (threadIdx.x < 128) {
        sc[threadIdx.x] = g_bnp[threadIdx.x];
        sb[threadIdx.x] = g_bnp[128 + threadIdx.x];
    }
    __syncthreads();
    const int total4 = n_rows * OUTC / 4;
    for (int i = blockIdx.x * blockDim.x + threadIdx.x; i < total4;
         i += gridDim.x * blockDim.x) {
        const int c0 = (i * 4) & 127;
        float4 v = *((const float4*)t + i);
        float4 o;
        o.x = v.x * sc[c0]     + sb[c0];
        o.y = v.y * sc[c0 + 1] + sb[c0 + 1];
        o.z = v.z * sc[c0 + 2] + sb[c0 + 2];
        o.w = v.w * sc[c0 + 3] + sb[c0 + 3];
        o.x = (o.x >= 0.f) ? o.x : 0.2f * o.x;
        o.y = (o.y >= 0.f) ? o.y : 0.2f * o.y;
        o.z = (o.z >= 0.f) ? o.z : 0.2f * o.z;
        o.w = (o.w >= 0.f) ? o.w : 0.2f * o.w;
        if (CVT) { o.x = f2tf32(o.x); o.y = f2tf32(o.y); o.z = f2tf32(o.z); o.w = f2tf32(o.w); }
        *((float4*)out + i) = o;
    }
}

// ---------------- launch ----------------
extern "C" void kernel_launch(void* const* d_in, const int* in_sizes, int n_in,
                              void* d_out, int out_size) {
    const float* x    = (const float*)d_in[0];
    const int*   nraw = (const int*)d_in[1];
    const int*   praw = (const int*)d_in[2];
    const float* W1   = (const float*)d_in[3];
    const float* b1   = (const float*)d_in[4];
    const float* g1   = (const float*)d_in[5];
    const float* be1  = (const float*)d_in[6];
    const float* W2   = (const float*)d_in[7];
    const float* b2   = (const float*)d_in[8];
    const float* g2   = (const float*)d_in[9];
    const float* be2  = (const float*)d_in[10];
    float* out = (float*)d_out;

    int *p_neigh, *p_pool;
    float *p_pooled, *p_t1, *p_h, *p_t2, *p_w1, *p_w2, *p_part;
    cudaGetSymbolAddress((void**)&p_neigh,  g_neigh);
    cudaGetSymbolAddress((void**)&p_pool,   g_pool);
    cudaGetSymbolAddress((void**)&p_pooled, g_pooled);
    cudaGetSymbolAddress((void**)&p_t1,     g_t1);
    cudaGetSymbolAddress((void**)&p_h,      g_h);
    cudaGetSymbolAddress((void**)&p_t2,     g_t2);
    cudaGetSymbolAddress((void**)&p_w1,     g_w1);
    cudaGetSymbolAddress((void**)&p_w2,     g_w2);
    cudaGetSymbolAddress((void**)&p_part,   g_part);

    const int SMEM_DYN = 2 * (128 * 36 + 32 * 136) * (int)sizeof(float);  // 71680
    cudaFuncSetAttribute(gather_gemm_tf32<64>,
                         cudaFuncAttributeMaxDynamicSharedMemorySize, SMEM_DYN);
    cudaFuncSetAttribute(gather_gemm_tf32<128>,
                         cudaFuncAttributeMaxDynamicSharedMemorySize, SMEM_DYN);

    convert_idx_kernel<<<112, 256>>>(nraw, p_neigh, NIDX);
    convert_idx_kernel<<<112, 256>>>(praw, p_pool,  NIDX);
    wconv_kernel<<<(448 * 128 + 896 * 128 + 255) / 256, 256>>>(W1, W2);

    pool_kernel<<<(N_OUT + 15) / 16, 256>>>(x);

    gather_gemm_tf32<64><<<GEMM_GRID, 256, SMEM_DYN>>>(p_pooled, p_neigh, p_w1, b1, p_t1, p_part);
    finalize_kernel<<<1, 128>>>(g1, be1, N_OUT);
    bn_kernel<true><<<512, 256>>>(p_t1, p_h, N_OUT);

    gather_gemm_tf32<128><<<GEMM_GRID, 256, SMEM_DYN>>>(p_h, p_neigh, p_w2, b2, p_t2, p_part);
    finalize_kernel<<<1, 128>>>(g2, be2, N_OUT);
    bn_kernel<false><<<512, 256>>>(p_t2, out, N_OUT);
}